// round 2
// baseline (speedup 1.0000x reference)
#include <cuda_runtime.h>
#include <math.h>
#include <stdint.h>

#define Bz   2
#define Nn   1024
#define Hh   768
#define Ss   30285
#define Kk   409
#define MAXW 30
#define WD   20
// W1 row offsets
#define WX_OFF 0
#define WY_OFF (768*768)
#define WXY_OFF (1536*768)
#define WW_ROW 2304

// -------- scratch (static __device__, no allocations) --------
__device__ float    g_P[Bz*Nn*Hh];          // emb @ Wx
__device__ float    g_Q[Bz*Nn*Hh];          // emb @ Wy
__device__ float    g_R[MAXW*Hh];           // width @ Ww + b1
__device__ float    g_H[(size_t)Bz*Ss*Hh];  // gelu(pre)  ~186MB
__device__ float    g_scores[Bz*Ss];
__device__ unsigned g_keys[Bz*Ss];
__device__ int      g_len[Bz];
__device__ unsigned g_thr[Bz];
__device__ int      g_gt[Bz*Kk];
__device__ int      g_eq[Bz*Ss];
__device__ int      g_sel[Bz*Kk];

// ---------------- lengths = sum(mask) ----------------
__global__ void len_kernel(const int* __restrict__ mask) {
    __shared__ int red[256];
    int b = blockIdx.x, tid = threadIdx.x;
    int p = 0;
    for (int i = tid; i < Nn; i += 256) p += mask[b*Nn + i];
    red[tid] = p; __syncthreads();
    for (int s = 128; s > 0; s >>= 1) { if (tid < s) red[tid] += red[tid+s]; __syncthreads(); }
    if (tid == 0) g_len[b] = red[0];
}

// ---------------- R[w] = width_emb[w] @ Ww + b1 ----------------
__global__ void r_kernel(const float* __restrict__ wemb,
                         const float* __restrict__ W1,
                         const float* __restrict__ b1) {
    int w = blockIdx.x;
    for (int c = threadIdx.x; c < Hh; c += blockDim.x) {
        float a = b1[c];
        #pragma unroll
        for (int j = 0; j < WD; j++) a += wemb[w*WD + j] * W1[(WW_ROW + j)*Hh + c];
        g_R[w*Hh + c] = a;
    }
}

// ---------------- tiled SGEMM, fp32x2 FFMA2 ----------------
// MODE 0: C[m,:] = emb[m,:] @ W  (dest: g_P if dest==0 else g_Q)
// MODE 1: pre = (x ⊙ y) @ Wxy + P + Q + R ; g_H = gelu(pre)
template <int MODE>
__global__ void __launch_bounds__(256)
sgemm_kernel(const float* __restrict__ emb, const int* __restrict__ spans,
             const float* __restrict__ W, int Mrows, int dest) {
    __shared__ float As[8][128];
    __shared__ float Bs[8][128];
    __shared__ int sXo[128], sYo[128], sRo[128];

    const int tid = threadIdx.x;
    const int n0 = blockIdx.x * 128;
    const int m0 = blockIdx.y * 128;

    if (tid < 128) {
        int m = m0 + tid;
        if (MODE == 0) {
            sXo[tid] = (m < Mrows) ? m*Hh : -1;
            sYo[tid] = 0; sRo[tid] = 0;
        } else {
            if (m < Mrows) {
                int b = m / Ss, sid = m - b*Ss;
                int s = spans[2*sid], e = spans[2*sid+1];
                sXo[tid] = (b*Nn + s)*Hh;
                sYo[tid] = (b*Nn + e)*Hh;
                sRo[tid] = (e - s)*Hh;
            } else { sXo[tid] = -1; sYo[tid] = 0; sRo[tid] = 0; }
        }
    }
    __syncthreads();

    const int tx = tid & 15, ty = tid >> 4;
    const int ar = tid >> 1, ac = (tid & 1) * 4;
    const int br = tid >> 5, bc = (tid & 31) * 4;

    const int xoRaw = sXo[ar];
    const int Xo = (xoRaw < 0) ? 0 : xoRaw;
    const int Yo = (MODE == 1) ? sYo[ar] : 0;

    unsigned long long acc[8][4];
    #pragma unroll
    for (int i = 0; i < 8; i++)
        #pragma unroll
        for (int j = 0; j < 4; j++) acc[i][j] = 0ULL;

    for (int k0 = 0; k0 < Hh; k0 += 8) {
        float4 xv = *(const float4*)(emb + Xo + k0 + ac);
        if (MODE == 1) {
            float4 yv = *(const float4*)(emb + Yo + k0 + ac);
            xv.x *= yv.x; xv.y *= yv.y; xv.z *= yv.z; xv.w *= yv.w;
        }
        As[ac+0][ar] = xv.x; As[ac+1][ar] = xv.y;
        As[ac+2][ar] = xv.z; As[ac+3][ar] = xv.w;
        *(float4*)&Bs[br][bc] = *(const float4*)(W + (size_t)(k0 + br)*Hh + n0 + bc);
        __syncthreads();

        #pragma unroll
        for (int kk = 0; kk < 8; kk++) {
            float4 a0 = *(float4*)&As[kk][ty*8];
            float4 a1 = *(float4*)&As[kk][ty*8 + 4];
            ulonglong2 b01 = *(ulonglong2*)&Bs[kk][tx*8];
            ulonglong2 b23 = *(ulonglong2*)&Bs[kk][tx*8 + 4];
            float av[8] = {a0.x,a0.y,a0.z,a0.w,a1.x,a1.y,a1.z,a1.w};
            unsigned long long bp[4] = {b01.x, b01.y, b23.x, b23.y};
            #pragma unroll
            for (int i = 0; i < 8; i++) {
                unsigned long long ad;
                asm("mov.b64 %0, {%1,%1};" : "=l"(ad) : "f"(av[i]));
                #pragma unroll
                for (int j = 0; j < 4; j++)
                    asm("fma.rn.f32x2 %0, %1, %2, %0;" : "+l"(acc[i][j]) : "l"(ad), "l"(bp[j]));
            }
        }
        __syncthreads();
    }

    // epilogue
    #pragma unroll
    for (int i = 0; i < 8; i++) {
        int r = ty*8 + i;
        int xo = sXo[r];
        if (xo < 0) continue;
        int m = m0 + r;
        float out[8];
        #pragma unroll
        for (int j = 0; j < 4; j++) {
            float lo, hi;
            asm("mov.b64 {%0,%1}, %2;" : "=f"(lo), "=f"(hi) : "l"(acc[i][j]));
            out[2*j] = lo; out[2*j+1] = hi;
        }
        int col0 = n0 + tx*8;
        if (MODE == 0) {
            float* C = dest ? g_Q : g_P;
            *(float4*)&C[(size_t)m*Hh + col0]     = make_float4(out[0],out[1],out[2],out[3]);
            *(float4*)&C[(size_t)m*Hh + col0 + 4] = make_float4(out[4],out[5],out[6],out[7]);
        } else {
            int yo = sYo[r], ro = sRo[r];
            #pragma unroll
            for (int j = 0; j < 8; j++) {
                int c = col0 + j;
                float pre = out[j] + g_P[xo + c] + g_Q[yo + c] + g_R[ro + c];
                out[j] = 0.5f * pre * (1.0f + erff(pre * 0.70710678118654752f));
            }
            *(float4*)&g_H[(size_t)m*Hh + col0]     = make_float4(out[0],out[1],out[2],out[3]);
            *(float4*)&g_H[(size_t)m*Hh + col0 + 4] = make_float4(out[4],out[5],out[6],out[7]);
        }
    }
}

// ---------------- scores = h · w_s + b_s (+mask penalty), sortable keys ----------------
__global__ void score_kernel(const int* __restrict__ spans,
                             const float* __restrict__ w_s,
                             const float* __restrict__ b_s) {
    __shared__ float red[256];
    int sid = blockIdx.x, b = blockIdx.y, tid = threadIdx.x;
    const float* hr = g_H + (size_t)(b*Ss + sid) * Hh;
    float p = 0.f;
    for (int c = tid; c < Hh; c += 256) p += hr[c] * w_s[c];
    red[tid] = p; __syncthreads();
    for (int s = 128; s > 0; s >>= 1) { if (tid < s) red[tid] += red[tid+s]; __syncthreads(); }
    if (tid == 0) {
        float sc = red[0] + b_s[0];
        int e = spans[2*sid + 1];
        if (e >= g_len[b]) sc += -1000000.0f;
        g_scores[b*Ss + sid] = sc;
        unsigned u = __float_as_uint(sc);
        g_keys[b*Ss + sid] = (u & 0x80000000u) ? ~u : (u | 0x80000000u);
    }
}

// ---------------- exact kth-largest key via 4-pass radix ----------------
__global__ void radix_kernel(int k) {
    __shared__ int hist[256];
    __shared__ unsigned s_prefix, s_mask;
    __shared__ int s_kneed;
    int b = blockIdx.x, tid = threadIdx.x;
    if (tid == 0) { s_prefix = 0u; s_mask = 0u; s_kneed = k; }
    __syncthreads();
    for (int shift = 24; shift >= 0; shift -= 8) {
        for (int i = tid; i < 256; i += blockDim.x) hist[i] = 0;
        __syncthreads();
        unsigned pm = s_mask, pf = s_prefix;
        for (int i = tid; i < Ss; i += blockDim.x) {
            unsigned key = g_keys[b*Ss + i];
            if ((key & pm) == pf) atomicAdd(&hist[(key >> shift) & 255], 1);
        }
        __syncthreads();
        if (tid == 0) {
            int cum = 0, kn = s_kneed;
            for (int bin = 255; bin >= 0; bin--) {
                int h = hist[bin];
                if (kn <= cum + h) {
                    s_prefix = pf | ((unsigned)bin << shift);
                    s_kneed = kn - cum;
                    s_mask  = pm | (0xFFu << shift);
                    break;
                }
                cum += h;
            }
        }
        __syncthreads();
    }
    if (tid == 0) g_thr[b] = s_prefix;
}

// ---------------- select k indices (ties -> lowest idx), sort ascending ----------------
__global__ void select_kernel(int k) {
    __shared__ int c_gt, c_eq;
    __shared__ int sel[512];
    int b = blockIdx.x, tid = threadIdx.x;
    if (tid == 0) { c_gt = 0; c_eq = 0; }
    sel[tid] = 0x7FFFFFFF;
    __syncthreads();
    unsigned T = g_thr[b];
    for (int i = tid; i < Ss; i += 512) {
        unsigned key = g_keys[b*Ss + i];
        if (key > T)       { int p = atomicAdd(&c_gt, 1); g_gt[b*Kk + p] = i; }
        else if (key == T) { int p = atomicAdd(&c_eq, 1); g_eq[b*Ss + p] = i; }
    }
    __syncthreads();
    int gt = c_gt, eq = c_eq, need = k - gt;
    if (tid < gt) sel[tid] = g_gt[b*Kk + tid];
    for (int j = tid; j < eq; j += 512) {
        int my = g_eq[b*Ss + j];
        int rank = 0;
        for (int l = 0; l < eq; l++) rank += (g_eq[b*Ss + l] < my);
        if (rank < need) sel[gt + rank] = my;
    }
    __syncthreads();
    // bitonic sort 512 ascending
    for (int sz = 2; sz <= 512; sz <<= 1) {
        for (int j = sz >> 1; j > 0; j >>= 1) {
            int i = tid, ixj = i ^ j;
            if (ixj > i) {
                bool up = ((i & sz) == 0);
                int a = sel[i], c = sel[ixj];
                if ((a > c) == up) { sel[i] = c; sel[ixj] = a; }
            }
            __syncthreads();
        }
    }
    if (tid < k) g_sel[b*Kk + tid] = sel[tid];
}

// ---------------- gather outputs ----------------
// layout: [embs B*K*H][scores B*K][spans B*K*2 as float]
__global__ void gather_kernel(const int* __restrict__ spans, float* __restrict__ out) {
    int j = blockIdx.x, b = blockIdx.y, tid = threadIdx.x;
    int idx = g_sel[b*Kk + j];
    const float* src = g_H + (size_t)(b*Ss + idx) * Hh;
    float* dst = out + (size_t)(b*Kk + j) * Hh;
    for (int c = tid; c < Hh; c += blockDim.x) dst[c] = src[c];
    if (tid == 0) {
        size_t sc_base = (size_t)Bz*Kk*Hh;
        out[sc_base + b*Kk + j] = g_scores[b*Ss + idx];
        size_t sp_base = sc_base + (size_t)Bz*Kk;
        int s = spans[2*idx], e = spans[2*idx + 1];
        out[sp_base + (size_t)(b*Kk + j)*2]     = (float)s;
        out[sp_base + (size_t)(b*Kk + j)*2 + 1] = (float)e;
    }
}

__global__ void fill_tail_kernel(float* out, long long begin, long long end) {
    long long i = begin + blockIdx.x * (long long)blockDim.x + threadIdx.x;
    if (i < end) out[i] = 0.0f;
}

extern "C" void kernel_launch(void* const* d_in, const int* in_sizes, int n_in,
                              void* d_out, int out_size) {
    const float* emb   = (const float*)d_in[0];
    const int*   mask  = (const int*)  d_in[1];
    const int*   spans = (const int*)  d_in[2];
    const float* wemb  = (const float*)d_in[3];
    const float* W1    = (const float*)d_in[4];
    const float* b1    = (const float*)d_in[5];
    const float* w_s   = (const float*)d_in[6];
    const float* b_s   = (const float*)d_in[7];
    float* out = (float*)d_out;
    (void)n_in; (void)in_sizes;

    // zero any tail beyond what we write (in case of padding in out buffer)
    long long written = (long long)Bz*Kk*Hh + (long long)Bz*Kk + (long long)Bz*Kk*2;
    if ((long long)out_size > written) {
        long long extra = (long long)out_size - written;
        int blocks = (int)((extra + 255) / 256);
        fill_tail_kernel<<<blocks, 256>>>(out, written, (long long)out_size);
    }

    len_kernel<<<Bz, 256>>>(mask);
    r_kernel<<<MAXW, 256>>>(wemb, W1, b1);

    // P = emb @ Wx, Q = emb @ Wy   (M = B*N = 2048)
    sgemm_kernel<0><<<dim3(Hh/128, (Bz*Nn)/128), 256>>>(emb, spans, W1 + WX_OFF, Bz*Nn, 0);
    sgemm_kernel<0><<<dim3(Hh/128, (Bz*Nn)/128), 256>>>(emb, spans, W1 + WY_OFF, Bz*Nn, 1);

    // fused main GEMM: h = gelu((x*y)@Wxy + P + Q + R)
    int mblocks = (Bz*Ss + 127) / 128;
    sgemm_kernel<1><<<dim3(Hh/128, mblocks), 256>>>(emb, spans, W1 + WXY_OFF, Bz*Ss, 0);

    score_kernel<<<dim3(Ss, Bz), 256>>>(spans, w_s, b_s);
    radix_kernel<<<Bz, 256>>>(Kk);
    select_kernel<<<Bz, 512>>>(Kk);
    gather_kernel<<<dim3(Kk, Bz), 192>>>(spans, out);
}

// round 3
// speedup vs baseline: 1.0497x; 1.0497x over previous
#include <cuda_runtime.h>
#include <math.h>
#include <stdint.h>

#define Bz   2
#define Nn   1024
#define Hh   768
#define Ss   30285
#define Kk   409
#define MAXW 30
#define WD   20
#define NBLK 6                   // Hh/128
#define MPAD 60672               // ceil(Bz*Ss/128)*128
#define WY_OFF (768*768)
#define WXY_OFF (1536*768)
#define WW_ROW 2304

// -------- scratch (static __device__, no allocations) --------
__device__ float    g_P[Bz*Nn*Hh];
__device__ float    g_Q[Bz*Nn*Hh];
__device__ float    g_R[MAXW*Hh];
__device__ float    g_part[NBLK*MPAD];   // score partials [nblk][row]
__device__ float    g_scores[Bz*Ss];
__device__ unsigned g_keys[Bz*Ss];
__device__ int      g_len[Bz];
__device__ unsigned g_thr[Bz];
__device__ int      g_gt[Bz*Kk];
__device__ int      g_eq[Bz*Ss];
__device__ int      g_sel[Bz*Kk];

// ---------------- lengths ----------------
__global__ void len_kernel(const int* __restrict__ mask) {
    __shared__ int red[256];
    int b = blockIdx.x, tid = threadIdx.x;
    int p = 0;
    for (int i = tid; i < Nn; i += 256) p += mask[b*Nn + i];
    red[tid] = p; __syncthreads();
    for (int s = 128; s > 0; s >>= 1) { if (tid < s) red[tid] += red[tid+s]; __syncthreads(); }
    if (tid == 0) g_len[b] = red[0];
}

// ---------------- R[w] = width_emb[w] @ Ww + b1 ----------------
__global__ void r_kernel(const float* __restrict__ wemb,
                         const float* __restrict__ W1,
                         const float* __restrict__ b1) {
    int w = blockIdx.x;
    for (int c = threadIdx.x; c < Hh; c += blockDim.x) {
        float a = b1[c];
        #pragma unroll
        for (int j = 0; j < WD; j++) a += wemb[w*WD + j] * W1[(WW_ROW + j)*Hh + c];
        g_R[w*Hh + c] = a;
    }
}

// ---------------- tiled SGEMM, fp32x2, double-buffered ----------------
// MODE 0: C = emb @ W (z=0 -> g_P with Wx, z=1 -> g_Q with Wy)
// MODE 1: pre = (x⊙y)@Wxy + P+Q+R; h=gelu(pre); write score partials only
// MODE 2: rows = selected spans; recompute h exactly, write to out
template <int MODE>
__global__ void __launch_bounds__(256)
sgemm_kernel(const float* __restrict__ emb, const int* __restrict__ spans,
             const float* __restrict__ W, int Mrows,
             const float* __restrict__ ws, float* __restrict__ out) {
    __shared__ float As[2][8][128];
    __shared__ float Bs[2][8][128];
    __shared__ int sXo[128], sYo[128], sRo[128];
    __shared__ float red[128][17];

    const int tid = threadIdx.x;
    const int n0 = blockIdx.x * 128;
    const int m0 = blockIdx.y * 128;
    const float* Wp = (MODE == 0) ? (W + blockIdx.z * (768*768)) : W;

    if (tid < 128) {
        int m = m0 + tid;
        if (MODE == 0) {
            sXo[tid] = (m < Mrows) ? m*Hh : -1;
            sYo[tid] = 0; sRo[tid] = 0;
        } else {
            int sid = -1, b = 0;
            if (m < Mrows) {
                if (MODE == 1) { b = m / Ss; sid = m - b*Ss; }
                else           { b = m / Kk; sid = g_sel[m]; }
            }
            if (sid >= 0) {
                int s = spans[2*sid], e = spans[2*sid+1];
                sXo[tid] = (b*Nn + s)*Hh;
                sYo[tid] = (b*Nn + e)*Hh;
                sRo[tid] = (e - s)*Hh;
            } else { sXo[tid] = -1; sYo[tid] = 0; sRo[tid] = 0; }
        }
    }
    __syncthreads();

    const int tx = tid & 15, ty = tid >> 4;
    const int ar = tid >> 1, ac = (tid & 1) * 4;
    const int br = tid >> 5, bc = (tid & 31) * 4;

    const int xoRaw = sXo[ar];
    const int Xo = (xoRaw < 0) ? 0 : xoRaw;
    const int Yo = (MODE != 0) ? sYo[ar] : 0;

    unsigned long long acc[8][4];
    #pragma unroll
    for (int i = 0; i < 8; i++)
        #pragma unroll
        for (int j = 0; j < 4; j++) acc[i][j] = 0ULL;

    float wsr[8];
    if (MODE == 1) {
        #pragma unroll
        for (int j = 0; j < 8; j++) wsr[j] = ws[n0 + tx*8 + j];
    }

    // prologue: load chunk 0
    float4 xv = *(const float4*)(emb + Xo + ac);
    if (MODE != 0) {
        float4 yv = *(const float4*)(emb + Yo + ac);
        xv.x *= yv.x; xv.y *= yv.y; xv.z *= yv.z; xv.w *= yv.w;
    }
    float4 bv = *(const float4*)(Wp + (size_t)br*Hh + n0 + bc);
    As[0][ac+0][ar] = xv.x; As[0][ac+1][ar] = xv.y;
    As[0][ac+2][ar] = xv.z; As[0][ac+3][ar] = xv.w;
    *(float4*)&Bs[0][br][bc] = bv;
    __syncthreads();

    for (int k0 = 0; k0 < Hh; k0 += 8) {
        const int p = (k0 >> 3) & 1;
        const bool more = (k0 + 8) < Hh;
        float4 nxv, nbv;
        if (more) {
            nxv = *(const float4*)(emb + Xo + k0 + 8 + ac);
            if (MODE != 0) {
                float4 yv = *(const float4*)(emb + Yo + k0 + 8 + ac);
                nxv.x *= yv.x; nxv.y *= yv.y; nxv.z *= yv.z; nxv.w *= yv.w;
            }
            nbv = *(const float4*)(Wp + (size_t)(k0 + 8 + br)*Hh + n0 + bc);
        }
        #pragma unroll
        for (int kk = 0; kk < 8; kk++) {
            float4 a0 = *(float4*)&As[p][kk][ty*8];
            float4 a1 = *(float4*)&As[p][kk][ty*8 + 4];
            ulonglong2 b01 = *(ulonglong2*)&Bs[p][kk][tx*8];
            ulonglong2 b23 = *(ulonglong2*)&Bs[p][kk][tx*8 + 4];
            float av[8] = {a0.x,a0.y,a0.z,a0.w,a1.x,a1.y,a1.z,a1.w};
            unsigned long long bp[4] = {b01.x, b01.y, b23.x, b23.y};
            #pragma unroll
            for (int i = 0; i < 8; i++) {
                unsigned long long ad;
                asm("mov.b64 %0, {%1,%1};" : "=l"(ad) : "f"(av[i]));
                #pragma unroll
                for (int j = 0; j < 4; j++)
                    asm("fma.rn.f32x2 %0, %1, %2, %0;" : "+l"(acc[i][j]) : "l"(ad), "l"(bp[j]));
            }
        }
        if (more) {
            As[p^1][ac+0][ar] = nxv.x; As[p^1][ac+1][ar] = nxv.y;
            As[p^1][ac+2][ar] = nxv.z; As[p^1][ac+3][ar] = nxv.w;
            *(float4*)&Bs[p^1][br][bc] = nbv;
        }
        __syncthreads();
    }

    // epilogue
    #pragma unroll
    for (int i = 0; i < 8; i++) {
        int r = ty*8 + i;
        int xo = sXo[r];
        int m = m0 + r;
        float o[8];
        #pragma unroll
        for (int j = 0; j < 4; j++) {
            float lo, hi;
            asm("mov.b64 {%0,%1}, %2;" : "=f"(lo), "=f"(hi) : "l"(acc[i][j]));
            o[2*j] = lo; o[2*j+1] = hi;
        }
        int col0 = n0 + tx*8;
        if (MODE == 0) {
            if (xo >= 0) {
                float* C = blockIdx.z ? g_Q : g_P;
                *(float4*)&C[(size_t)m*Hh + col0]     = make_float4(o[0],o[1],o[2],o[3]);
                *(float4*)&C[(size_t)m*Hh + col0 + 4] = make_float4(o[4],o[5],o[6],o[7]);
            }
        } else {
            float partial = 0.f;
            if (xo >= 0) {
                int yo = sYo[r], ro = sRo[r];
                #pragma unroll
                for (int j = 0; j < 8; j++) {
                    int c = col0 + j;
                    float pre = o[j] + g_P[xo + c] + g_Q[yo + c] + g_R[ro + c];
                    o[j] = 0.5f * pre * (1.0f + erff(pre * 0.70710678118654752f));
                }
                if (MODE == 1) {
                    #pragma unroll
                    for (int j = 0; j < 8; j++) partial += o[j] * wsr[j];
                } else {
                    *(float4*)&out[(size_t)m*Hh + col0]     = make_float4(o[0],o[1],o[2],o[3]);
                    *(float4*)&out[(size_t)m*Hh + col0 + 4] = make_float4(o[4],o[5],o[6],o[7]);
                }
            }
            if (MODE == 1) red[r][tx] = partial;
        }
    }
    if (MODE == 1) {
        __syncthreads();
        if (tid < 128) {
            float s = 0.f;
            #pragma unroll
            for (int j = 0; j < 16; j++) s += red[tid][j];
            if (sXo[tid] >= 0)
                g_part[(size_t)blockIdx.x * MPAD + (m0 + tid)] = s;
        }
    }
}

// ---------------- scores = sum(partials) + b_s + mask, sortable keys ----------------
__global__ void score_reduce_kernel(const int* __restrict__ spans,
                                    const float* __restrict__ b_s) {
    int i = blockIdx.x * 256 + threadIdx.x;
    if (i >= Bz*Ss) return;
    int b = i / Ss, sid = i - b*Ss;
    float sc = b_s[0];
    #pragma unroll
    for (int j = 0; j < NBLK; j++) sc += g_part[(size_t)j * MPAD + i];
    int e = spans[2*sid + 1];
    if (e >= g_len[b]) sc += -1000000.0f;
    g_scores[i] = sc;
    unsigned u = __float_as_uint(sc);
    g_keys[i] = (u & 0x80000000u) ? ~u : (u | 0x80000000u);
}

// ---------------- exact kth-largest key via 4-pass radix ----------------
__global__ void radix_kernel(int k) {
    __shared__ int hist[256];
    __shared__ unsigned s_prefix, s_mask;
    __shared__ int s_kneed;
    int b = blockIdx.x, tid = threadIdx.x;
    if (tid == 0) { s_prefix = 0u; s_mask = 0u; s_kneed = k; }
    __syncthreads();
    for (int shift = 24; shift >= 0; shift -= 8) {
        for (int i = tid; i < 256; i += blockDim.x) hist[i] = 0;
        __syncthreads();
        unsigned pm = s_mask, pf = s_prefix;
        for (int i = tid; i < Ss; i += blockDim.x) {
            unsigned key = g_keys[b*Ss + i];
            if ((key & pm) == pf) atomicAdd(&hist[(key >> shift) & 255], 1);
        }
        __syncthreads();
        if (tid == 0) {
            int cum = 0, kn = s_kneed;
            for (int bin = 255; bin >= 0; bin--) {
                int h = hist[bin];
                if (kn <= cum + h) {
                    s_prefix = pf | ((unsigned)bin << shift);
                    s_kneed = kn - cum;
                    s_mask  = pm | (0xFFu << shift);
                    break;
                }
                cum += h;
            }
        }
        __syncthreads();
    }
    if (tid == 0) g_thr[b] = s_prefix;
}

// ---------------- select k indices (ties -> lowest idx), sort ascending ----------------
__global__ void select_kernel(int k) {
    __shared__ int c_gt, c_eq;
    __shared__ int sel[512];
    int b = blockIdx.x, tid = threadIdx.x;
    if (tid == 0) { c_gt = 0; c_eq = 0; }
    sel[tid] = 0x7FFFFFFF;
    __syncthreads();
    unsigned T = g_thr[b];
    for (int i = tid; i < Ss; i += 512) {
        unsigned key = g_keys[b*Ss + i];
        if (key > T)       { int p = atomicAdd(&c_gt, 1); g_gt[b*Kk + p] = i; }
        else if (key == T) { int p = atomicAdd(&c_eq, 1); g_eq[b*Ss + p] = i; }
    }
    __syncthreads();
    int gt = c_gt, eq = c_eq, need = k - gt;
    if (tid < gt) sel[tid] = g_gt[b*Kk + tid];
    for (int j = tid; j < eq; j += 512) {
        int my = g_eq[b*Ss + j];
        int rank = 0;
        for (int l = 0; l < eq; l++) rank += (g_eq[b*Ss + l] < my);
        if (rank < need) sel[gt + rank] = my;
    }
    __syncthreads();
    for (int sz = 2; sz <= 512; sz <<= 1) {
        for (int j = sz >> 1; j > 0; j >>= 1) {
            int i = tid, ixj = i ^ j;
            if (ixj > i) {
                bool up = ((i & sz) == 0);
                int a = sel[i], c = sel[ixj];
                if ((a > c) == up) { sel[i] = c; sel[ixj] = a; }
            }
            __syncthreads();
        }
    }
    if (tid < k) g_sel[b*Kk + tid] = sel[tid];
}

// ---------------- scores/spans -> out ----------------
__global__ void gather_meta_kernel(const int* __restrict__ spans, float* __restrict__ out) {
    int t = blockIdx.x * 256 + threadIdx.x;
    if (t >= Bz*Kk) return;
    int b = t / Kk;
    int idx = g_sel[t];
    size_t sc_base = (size_t)Bz*Kk*Hh;
    out[sc_base + t] = g_scores[b*Ss + idx];
    size_t sp_base = sc_base + (size_t)Bz*Kk;
    out[sp_base + (size_t)t*2]     = (float)spans[2*idx];
    out[sp_base + (size_t)t*2 + 1] = (float)spans[2*idx + 1];
}

__global__ void fill_tail_kernel(float* out, long long begin, long long end) {
    long long i = begin + blockIdx.x * (long long)blockDim.x + threadIdx.x;
    if (i < end) out[i] = 0.0f;
}

extern "C" void kernel_launch(void* const* d_in, const int* in_sizes, int n_in,
                              void* d_out, int out_size) {
    const float* emb   = (const float*)d_in[0];
    const int*   mask  = (const int*)  d_in[1];
    const int*   spans = (const int*)  d_in[2];
    const float* wemb  = (const float*)d_in[3];
    const float* W1    = (const float*)d_in[4];
    const float* b1    = (const float*)d_in[5];
    const float* w_s   = (const float*)d_in[6];
    const float* b_s   = (const float*)d_in[7];
    float* out = (float*)d_out;
    (void)n_in; (void)in_sizes;

    long long written = (long long)Bz*Kk*Hh + (long long)Bz*Kk + (long long)Bz*Kk*2;
    if ((long long)out_size > written) {
        long long extra = (long long)out_size - written;
        int blocks = (int)((extra + 255) / 256);
        fill_tail_kernel<<<blocks, 256>>>(out, written, (long long)out_size);
    }

    len_kernel<<<Bz, 256>>>(mask);
    r_kernel<<<MAXW, 256>>>(wemb, W1, b1);

    // P and Q in one launch (z = 0 -> Wx/g_P, z = 1 -> Wy/g_Q)
    sgemm_kernel<0><<<dim3(NBLK, (Bz*Nn)/128, 2), 256>>>(emb, spans, W1, Bz*Nn, nullptr, nullptr);

    // fused main GEMM: gelu pre + score partials (no h store)
    int mblocks = (Bz*Ss + 127) / 128;
    sgemm_kernel<1><<<dim3(NBLK, mblocks), 256>>>(emb, spans, W1 + WXY_OFF, Bz*Ss, w_s, nullptr);

    score_reduce_kernel<<<(Bz*Ss + 255)/256, 256>>>(spans, b_s);
    radix_kernel<<<Bz, 1024>>>(Kk);
    select_kernel<<<Bz, 512>>>(Kk);

    // recompute h exactly for the K selected spans, write straight to out
    int rb = (Bz*Kk + 127) / 128;
    sgemm_kernel<2><<<dim3(NBLK, rb), 256>>>(emb, spans, W1 + WXY_OFF, Bz*Kk, nullptr, out);

    gather_meta_kernel<<<(Bz*Kk + 255)/256, 256>>>(spans, out);
}

// round 5
// speedup vs baseline: 1.6519x; 1.5737x over previous
#include <cuda_runtime.h>
#include <cuda_bf16.h>
#include <math.h>
#include <stdint.h>

#define Bz   2
#define Nn   1024
#define Hh   768
#define Ss   30285
#define Kk   409
#define MAXW 30
#define WD   20
#define NBLK 6                    // 768/128
#define MTILES 474                // ceil(Bz*Ss/128)
#define MPAD (MTILES*128)
#define CAP  1024                 // candidate cap per batch
#define KEXT (Kk + 512)           // 921
#define WXY_OFF (1536*768)
#define WW_ROW 2304

// mma_main smem: 2 stages x 20480 bf16 (Ah,Al,Bh,Bl each 128x40) + meta
#define SA 40
#define STG 20480
#define MMA_SMEM (2*STG*2 + 1536 + 2048)   // 81920 + meta = 85504

__device__ __forceinline__ float gelu_exact(float x) {
    return 0.5f * x * (1.0f + erff(x * 0.70710678118654752f));
}

// ---------------- scratch ----------------
__device__ __nv_bfloat16 g_Wh[768*768];   // split-2 hi of Wxy, transposed [n][k]
__device__ __nv_bfloat16 g_Wl[768*768];   // split-2 lo
__device__ float    g_P[Bz*Nn*Hh];
__device__ float    g_Q[Bz*Nn*Hh];
__device__ float    g_R[MAXW*Hh];
__device__ float    g_part[NBLK*MPAD];
__device__ float    g_part2[NBLK*2*CAP];
__device__ float    g_scores[Bz*Ss];
__device__ unsigned g_keys[Bz*Ss];
__device__ int      g_len[Bz];
__device__ unsigned g_thr[Bz];
__device__ int      g_cand[Bz*CAP];
__device__ int      g_nc[Bz];
__device__ int      g_sel[Bz*Kk];

// ---------------- lengths ----------------
__global__ void len_kernel(const int* __restrict__ mask) {
    __shared__ int red[256];
    int b = blockIdx.x, tid = threadIdx.x;
    int p = 0;
    for (int i = tid; i < Nn; i += 256) p += mask[b*Nn + i];
    red[tid] = p; __syncthreads();
    for (int s = 128; s > 0; s >>= 1) { if (tid < s) red[tid] += red[tid+s]; __syncthreads(); }
    if (tid == 0) g_len[b] = red[0];
}

// ---------------- R[w] = width_emb[w] @ Ww + b1 (exact) ----------------
__global__ void r_kernel(const float* __restrict__ wemb,
                         const float* __restrict__ W1,
                         const float* __restrict__ b1) {
    int w = blockIdx.x;
    for (int c = threadIdx.x; c < Hh; c += blockDim.x) {
        float a = b1[c];
        #pragma unroll
        for (int j = 0; j < WD; j++) a += wemb[w*WD + j] * W1[(WW_ROW + j)*Hh + c];
        g_R[w*Hh + c] = a;
    }
}

// ---------------- Wxy -> transposed split-2 bf16 ----------------
__global__ void prep2_kernel(const float* __restrict__ W1) {
    int n = blockIdx.x;
    for (int k = threadIdx.x; k < 768; k += 256) {
        float v = W1[WXY_OFF + (size_t)k*768 + n];
        __nv_bfloat16 h = __float2bfloat16_rn(v);
        __nv_bfloat16 l = __float2bfloat16_rn(v - __bfloat162float(h));
        g_Wh[(size_t)n*768 + k] = h;
        g_Wl[(size_t)n*768 + k] = l;
    }
}

// ================= approx main GEMM: HMMA split-2 x 3 products =================
__device__ __forceinline__ void mma16816(float* c, const unsigned* a, const unsigned* b) {
    asm volatile("mma.sync.aligned.m16n8k16.row.col.f32.bf16.bf16.f32 "
        "{%0,%1,%2,%3}, {%4,%5,%6,%7}, {%8,%9}, {%0,%1,%2,%3};"
        : "+f"(c[0]), "+f"(c[1]), "+f"(c[2]), "+f"(c[3])
        : "r"(a[0]), "r"(a[1]), "r"(a[2]), "r"(a[3]), "r"(b[0]), "r"(b[1]));
}

__global__ void __launch_bounds__(256)
mma_main(const float* __restrict__ emb, const int* __restrict__ spans,
         const float* __restrict__ ws) {
    extern __shared__ __nv_bfloat16 sm[];
    int*   sXo = (int*)(sm + 2*STG);
    int*   sYo = sXo + 128;
    int*   sRo = sYo + 128;
    float* red = (float*)(sRo + 128);   // [128][4]

    const int tid = threadIdx.x, wid = tid >> 5, lane = tid & 31;
    const int n0 = blockIdx.x * 128;
    const int m0 = blockIdx.y * 128;
    const int g = lane >> 2, t = lane & 3;
    const int warpM = wid & 1, warpN = wid >> 1;

    if (tid < 128) {
        int m = m0 + tid;
        int sid = -1, b = 0;
        if (m < Bz*Ss) { b = m / Ss; sid = m - b*Ss; }
        if (sid >= 0) {
            int s = spans[2*sid], e = spans[2*sid + 1];
            sXo[tid] = (b*Nn + s)*Hh;
            sYo[tid] = (b*Nn + e)*Hh;
            sRo[tid] = (e - s)*Hh;
        } else { sXo[tid] = -1; sYo[tid] = 0; sRo[tid] = 0; }
    }
    __syncthreads();

    const int lr = tid >> 1;              // fill row 0..127
    const int lk = (tid & 1) * 16;        // fill k-offset
    const int xoF = sXo[lr];
    const bool fvalid = xoF >= 0;
    const float* xp = emb + (fvalid ? xoF : 0);
    const float* yp = emb + (fvalid ? sYo[lr] : 0);

    float acc[4][4][4];
    #pragma unroll
    for (int i = 0; i < 4; i++)
        #pragma unroll
        for (int j = 0; j < 4; j++)
            #pragma unroll
            for (int q = 0; q < 4; q++) acc[i][j][q] = 0.f;

    #pragma unroll 1
    for (int c = 0; c < 24; c++) {
        __nv_bfloat16* st = sm + (c & 1)*STG;
        // ---- fill A (x*y split2) + B (pre-split weights) ----
        {
            int kg = c*32 + lk;
            float v[16];
            #pragma unroll
            for (int q = 0; q < 4; q++) {
                float4 xa = *(const float4*)(xp + kg + 4*q);
                float4 ya = *(const float4*)(yp + kg + 4*q);
                v[4*q+0] = xa.x*ya.x; v[4*q+1] = xa.y*ya.y;
                v[4*q+2] = xa.z*ya.z; v[4*q+3] = xa.w*ya.w;
            }
            if (!fvalid) {
                #pragma unroll
                for (int q = 0; q < 16; q++) v[q] = 0.f;
            }
            unsigned hu[8], lu[8];
            #pragma unroll
            for (int q = 0; q < 8; q++) {
                __nv_bfloat16 h0 = __float2bfloat16_rn(v[2*q]);
                __nv_bfloat16 h1 = __float2bfloat16_rn(v[2*q+1]);
                __nv_bfloat16 l0 = __float2bfloat16_rn(v[2*q]   - __bfloat162float(h0));
                __nv_bfloat16 l1 = __float2bfloat16_rn(v[2*q+1] - __bfloat162float(h1));
                hu[q] = (unsigned)__bfloat16_as_ushort(h0) | ((unsigned)__bfloat16_as_ushort(h1) << 16);
                lu[q] = (unsigned)__bfloat16_as_ushort(l0) | ((unsigned)__bfloat16_as_ushort(l1) << 16);
            }
            int ao = lr*SA + lk;
            *(uint4*)(st + ao)            = make_uint4(hu[0],hu[1],hu[2],hu[3]);
            *(uint4*)(st + ao + 8)        = make_uint4(hu[4],hu[5],hu[6],hu[7]);
            *(uint4*)(st + 5120 + ao)     = make_uint4(lu[0],lu[1],lu[2],lu[3]);
            *(uint4*)(st + 5120 + ao + 8) = make_uint4(lu[4],lu[5],lu[6],lu[7]);
            size_t wo = (size_t)(n0 + lr)*768 + kg;
            const uint4* WH = (const uint4*)(g_Wh + wo);
            const uint4* WL = (const uint4*)(g_Wl + wo);
            *(uint4*)(st + 10240 + ao)     = WH[0];
            *(uint4*)(st + 10240 + ao + 8) = WH[1];
            *(uint4*)(st + 15360 + ao)     = WL[0];
            *(uint4*)(st + 15360 + ao + 8) = WL[1];
        }
        __syncthreads();
        // ---- MMA: 2 x k16 steps ----
        #pragma unroll
        for (int s = 0; s < 2; s++) {
            const int ko = s*16;
            unsigned ah[4][4], al[4][4];
            #pragma unroll
            for (int mt = 0; mt < 4; mt++) {
                int mb = warpM*64 + mt*16;
                int o0 = (mb + g)*SA + ko + 2*t;
                int o1 = (mb + g + 8)*SA + ko + 2*t;
                ah[mt][0] = *(const unsigned*)(st + o0);
                ah[mt][1] = *(const unsigned*)(st + o1);
                ah[mt][2] = *(const unsigned*)(st + o0 + 8);
                ah[mt][3] = *(const unsigned*)(st + o1 + 8);
                al[mt][0] = *(const unsigned*)(st + 5120 + o0);
                al[mt][1] = *(const unsigned*)(st + 5120 + o1);
                al[mt][2] = *(const unsigned*)(st + 5120 + o0 + 8);
                al[mt][3] = *(const unsigned*)(st + 5120 + o1 + 8);
            }
            unsigned bh[4][2], bl[4][2];
            #pragma unroll
            for (int nt = 0; nt < 4; nt++) {
                int nb2 = warpN*32 + nt*8;
                int o = (nb2 + g)*SA + ko + 2*t;
                bh[nt][0] = *(const unsigned*)(st + 10240 + o);
                bh[nt][1] = *(const unsigned*)(st + 10240 + o + 8);
                bl[nt][0] = *(const unsigned*)(st + 15360 + o);
                bl[nt][1] = *(const unsigned*)(st + 15360 + o + 8);
            }
            #pragma unroll
            for (int mt = 0; mt < 4; mt++)
                #pragma unroll
                for (int nt = 0; nt < 4; nt++) {
                    mma16816(acc[mt][nt], ah[mt], bh[nt]);
                    mma16816(acc[mt][nt], ah[mt], bl[nt]);
                    mma16816(acc[mt][nt], al[mt], bh[nt]);
                }
        }
        __syncthreads();
    }

    // ---- epilogue: +P+Q+R, gelu, score partial ----
    #pragma unroll
    for (int mt = 0; mt < 4; mt++) {
        #pragma unroll
        for (int rr = 0; rr < 2; rr++) {
            int ml = warpM*64 + mt*16 + g + rr*8;
            int xo2 = sXo[ml];
            float p = 0.f;
            if (xo2 >= 0) {
                int yo2 = sYo[ml], ro2 = sRo[ml];
                #pragma unroll
                for (int nt = 0; nt < 4; nt++) {
                    int n = n0 + warpN*32 + nt*8 + 2*t;
                    float2 Pv = *(const float2*)&g_P[xo2 + n];
                    float2 Qv = *(const float2*)&g_Q[yo2 + n];
                    float2 Rv = *(const float2*)&g_R[ro2 + n];
                    float2 Wv = *(const float2*)&ws[n];
                    float h0 = gelu_exact(acc[mt][nt][rr*2]   + Pv.x + Qv.x + Rv.x);
                    float h1 = gelu_exact(acc[mt][nt][rr*2+1] + Pv.y + Qv.y + Rv.y);
                    p += h0*Wv.x + h1*Wv.y;
                }
            }
            p += __shfl_xor_sync(0xffffffffu, p, 1);
            p += __shfl_xor_sync(0xffffffffu, p, 2);
            if (t == 0) red[ml*4 + warpN] = p;
        }
    }
    __syncthreads();
    if (tid < 128 && sXo[tid] >= 0)
        g_part[(size_t)blockIdx.x*MPAD + m0 + tid] =
            red[tid*4] + red[tid*4+1] + red[tid*4+2] + red[tid*4+3];
}

// ================= exact scalar fp32 GEMM (MODES 0/2/3) =================
// MODE 0: C = emb @ W (z=0 -> Wx/g_P, z=1 -> Wy/g_Q)
// MODE 2: rows = g_sel; exact h -> out
// MODE 3: rows = g_cand; exact score partials -> g_part2
template <int MODE>
__global__ void __launch_bounds__(256)
sgemm_kernel(const float* __restrict__ emb, const int* __restrict__ spans,
             const float* __restrict__ W, int Mrows,
             const float* __restrict__ ws, float* __restrict__ outp) {
    __shared__ float As[2][8][128];
    __shared__ float Bs[2][8][128];
    __shared__ int sXo[128], sYo[128], sRo[128];
    __shared__ float red[128][17];

    const int tid = threadIdx.x;
    const int n0 = blockIdx.x * 128;
    const int m0 = blockIdx.y * 128;
    const float* Wp = (MODE == 0) ? (W + blockIdx.z * (768*768)) : W;

    if (tid < 128) {
        int m = m0 + tid;
        if (MODE == 0) {
            sXo[tid] = (m < Mrows) ? m*Hh : -1;
            sYo[tid] = 0; sRo[tid] = 0;
        } else {
            int sid = -1, b = 0;
            if (MODE == 2) {
                if (m < Bz*Kk) { b = m / Kk; sid = g_sel[m]; }
            } else {
                b = m >> 10;
                int j = m & (CAP - 1);
                if (b < Bz && j < g_nc[b]) sid = g_cand[m] - b*Ss;
            }
            if (sid >= 0) {
                int s = spans[2*sid], e = spans[2*sid + 1];
                sXo[tid] = (b*Nn + s)*Hh;
                sYo[tid] = (b*Nn + e)*Hh;
                sRo[tid] = (e - s)*Hh;
            } else { sXo[tid] = -1; sYo[tid] = 0; sRo[tid] = 0; }
        }
    }
    __syncthreads();

    const int tx = tid & 15, ty = tid >> 4;
    const int ar = tid >> 1, ac = (tid & 1) * 4;
    const int br = tid >> 5, bc = (tid & 31) * 4;

    const int xoRaw = sXo[ar];
    const int Xo = (xoRaw < 0) ? 0 : xoRaw;
    const int Yo = (MODE != 0) ? ((xoRaw < 0) ? 0 : sYo[ar]) : 0;

    unsigned long long acc[8][4];
    #pragma unroll
    for (int i = 0; i < 8; i++)
        #pragma unroll
        for (int j = 0; j < 4; j++) acc[i][j] = 0ULL;

    float4 xv = *(const float4*)(emb + Xo + ac);
    if (MODE != 0) {
        float4 yv = *(const float4*)(emb + Yo + ac);
        xv.x *= yv.x; xv.y *= yv.y; xv.z *= yv.z; xv.w *= yv.w;
    }
    float4 bv = *(const float4*)(Wp + (size_t)br*Hh + n0 + bc);
    As[0][ac+0][ar] = xv.x; As[0][ac+1][ar] = xv.y;
    As[0][ac+2][ar] = xv.z; As[0][ac+3][ar] = xv.w;
    *(float4*)&Bs[0][br][bc] = bv;
    __syncthreads();

    for (int k0 = 0; k0 < Hh; k0 += 8) {
        const int p = (k0 >> 3) & 1;
        const bool more = (k0 + 8) < Hh;
        float4 nxv, nbv;
        if (more) {
            nxv = *(const float4*)(emb + Xo + k0 + 8 + ac);
            if (MODE != 0) {
                float4 yv = *(const float4*)(emb + Yo + k0 + 8 + ac);
                nxv.x *= yv.x; nxv.y *= yv.y; nxv.z *= yv.z; nxv.w *= yv.w;
            }
            nbv = *(const float4*)(Wp + (size_t)(k0 + 8 + br)*Hh + n0 + bc);
        }
        #pragma unroll
        for (int kk = 0; kk < 8; kk++) {
            float4 a0 = *(float4*)&As[p][kk][ty*8];
            float4 a1 = *(float4*)&As[p][kk][ty*8 + 4];
            ulonglong2 b01 = *(ulonglong2*)&Bs[p][kk][tx*8];
            ulonglong2 b23 = *(ulonglong2*)&Bs[p][kk][tx*8 + 4];
            float av[8] = {a0.x,a0.y,a0.z,a0.w,a1.x,a1.y,a1.z,a1.w};
            unsigned long long bp[4] = {b01.x, b01.y, b23.x, b23.y};
            #pragma unroll
            for (int i = 0; i < 8; i++) {
                unsigned long long ad;
                asm("mov.b64 %0, {%1,%1};" : "=l"(ad) : "f"(av[i]));
                #pragma unroll
                for (int j = 0; j < 4; j++)
                    asm("fma.rn.f32x2 %0, %1, %2, %0;" : "+l"(acc[i][j]) : "l"(ad), "l"(bp[j]));
            }
        }
        if (more) {
            As[p^1][ac+0][ar] = nxv.x; As[p^1][ac+1][ar] = nxv.y;
            As[p^1][ac+2][ar] = nxv.z; As[p^1][ac+3][ar] = nxv.w;
            *(float4*)&Bs[p^1][br][bc] = nbv;
        }
        __syncthreads();
    }

    #pragma unroll
    for (int i = 0; i < 8; i++) {
        int r = ty*8 + i;
        int xo = sXo[r];
        int m = m0 + r;
        float o[8];
        #pragma unroll
        for (int j = 0; j < 4; j++) {
            float lo, hi;
            asm("mov.b64 {%0,%1}, %2;" : "=f"(lo), "=f"(hi) : "l"(acc[i][j]));
            o[2*j] = lo; o[2*j+1] = hi;
        }
        int col0 = n0 + tx*8;
        if (MODE == 0) {
            if (xo >= 0) {
                float* C = blockIdx.z ? g_Q : g_P;
                *(float4*)&C[(size_t)m*Hh + col0]     = make_float4(o[0],o[1],o[2],o[3]);
                *(float4*)&C[(size_t)m*Hh + col0 + 4] = make_float4(o[4],o[5],o[6],o[7]);
            }
        } else {
            float partial = 0.f;
            if (xo >= 0) {
                int yo = sYo[r], ro = sRo[r];
                #pragma unroll
                for (int j = 0; j < 8; j++) {
                    int c = col0 + j;
                    float pre = o[j] + g_P[xo + c] + g_Q[yo + c] + g_R[ro + c];
                    o[j] = gelu_exact(pre);
                }
                if (MODE == 3) {
                    #pragma unroll
                    for (int j = 0; j < 8; j++) partial += o[j] * ws[col0 + j];
                } else {
                    *(float4*)&outp[(size_t)m*Hh + col0]     = make_float4(o[0],o[1],o[2],o[3]);
                    *(float4*)&outp[(size_t)m*Hh + col0 + 4] = make_float4(o[4],o[5],o[6],o[7]);
                }
            }
            if (MODE == 3) red[r][tx] = partial;
        }
    }
    if (MODE == 3) {
        __syncthreads();
        if (tid < 128) {
            float s = 0.f;
            #pragma unroll
            for (int j = 0; j < 16; j++) s += red[tid][j];
            if (sXo[tid] >= 0)
                g_part2[blockIdx.x*(2*CAP) + m0 + tid] = s;
        }
    }
}

// ---------------- approx score assemble ----------------
__global__ void score_reduce_kernel(const int* __restrict__ spans,
                                    const float* __restrict__ b_s) {
    int i = blockIdx.x * 256 + threadIdx.x;
    if (i >= Bz*Ss) return;
    int b = i / Ss, sid = i - b*Ss;
    float sc = b_s[0];
    #pragma unroll
    for (int j = 0; j < NBLK; j++) sc += g_part[(size_t)j * MPAD + i];
    int e = spans[2*sid + 1];
    if (e >= g_len[b]) sc += -1000000.0f;
    g_scores[i] = sc;
    unsigned u = __float_as_uint(sc);
    g_keys[i] = (u & 0x80000000u) ? ~u : (u | 0x80000000u);
}

// ---------------- kth-largest key (approx), 4-pass radix ----------------
__global__ void radix_kernel(int k) {
    __shared__ int hist[256];
    __shared__ unsigned s_prefix, s_mask;
    __shared__ int s_kneed;
    int b = blockIdx.x, tid = threadIdx.x;
    if (tid == 0) { s_prefix = 0u; s_mask = 0u; s_kneed = k; }
    __syncthreads();
    for (int shift = 24; shift >= 0; shift -= 8) {
        for (int i = tid; i < 256; i += blockDim.x) hist[i] = 0;
        __syncthreads();
        unsigned pm = s_mask, pf = s_prefix;
        for (int i = tid; i < Ss; i += blockDim.x) {
            unsigned key = g_keys[b*Ss + i];
            if ((key & pm) == pf) atomicAdd(&hist[(key >> shift) & 255], 1);
        }
        __syncthreads();
        if (tid == 0) {
            int cum = 0, kn = s_kneed;
            for (int bin = 255; bin >= 0; bin--) {
                int h = hist[bin];
                if (kn <= cum + h) {
                    s_prefix = pf | ((unsigned)bin << shift);
                    s_kneed = kn - cum;
                    s_mask  = pm | (0xFFu << shift);
                    break;
                }
                cum += h;
            }
        }
        __syncthreads();
    }
    if (tid == 0) g_thr[b] = s_prefix;
}

// ---------------- candidate filter ----------------
__global__ void filter_kernel() {
    __shared__ int cnt;
    int b = blockIdx.x, tid = threadIdx.x;
    if (tid == 0) cnt = 0;
    __syncthreads();
    unsigned T = g_thr[b];
    for (int i = tid; i < Ss; i += 1024) {
        if (g_keys[b*Ss + i] >= T) {
            int p = atomicAdd(&cnt, 1);
            if (p < CAP) g_cand[b*CAP + p] = b*Ss + i;
        }
    }
    __syncthreads();
    if (tid == 0) g_nc[b] = (cnt < CAP) ? cnt : CAP;
}

// ---------------- exact rescore assemble ----------------
__global__ void rescore_reduce(const int* __restrict__ spans,
                               const float* __restrict__ b_s) {
    int t = blockIdx.x * 256 + threadIdx.x;
    if (t >= Bz*CAP) return;
    int b = t >> 10, j = t & (CAP - 1);
    if (j >= g_nc[b]) return;
    int i = g_cand[t];
    float sc = b_s[0];
    #pragma unroll
    for (int nb = 0; nb < NBLK; nb++) sc += g_part2[nb*(2*CAP) + t];
    int sid = i - b*Ss;
    int e = spans[2*sid + 1];
    if (e >= g_len[b]) sc += -1000000.0f;
    g_scores[i] = sc;
    unsigned u = __float_as_uint(sc);
    g_keys[i] = (u & 0x80000000u) ? ~u : (u | 0x80000000u);
}

// ---------------- final exact selection (per batch) ----------------
__global__ void final_select_kernel() {
    __shared__ unsigned long long comp[CAP];
    __shared__ int sel2[512];
    int b = blockIdx.x, tid = threadIdx.x;
    int nc = g_nc[b];
    if (tid < nc) {
        int i = g_cand[b*CAP + tid];
        unsigned key = g_keys[i];
        comp[tid] = ((unsigned long long)(~key) << 32) | (unsigned)(i - b*Ss);
    } else {
        comp[tid] = 0xFFFFFFFFFFFFFFFFull;
    }
    __syncthreads();
    for (int sz = 2; sz <= CAP; sz <<= 1) {
        for (int j = sz >> 1; j > 0; j >>= 1) {
            int ix = tid ^ j;
            if (ix > tid) {
                bool up = ((tid & sz) == 0);
                unsigned long long a = comp[tid], c = comp[ix];
                if ((a > c) == up) { comp[tid] = c; comp[ix] = a; }
            }
            __syncthreads();
        }
    }
    if (tid < 512)
        sel2[tid] = (tid < Kk) ? (int)(unsigned)(comp[tid] & 0xFFFFFFFFull) : 0x7FFFFFFF;
    __syncthreads();
    for (int sz = 2; sz <= 512; sz <<= 1) {
        for (int j = sz >> 1; j > 0; j >>= 1) {
            if (tid < 512) {
                int ix = tid ^ j;
                if (ix > tid) {
                    bool up = ((tid & sz) == 0);
                    int a = sel2[tid], c = sel2[ix];
                    if ((a > c) == up) { sel2[tid] = c; sel2[ix] = a; }
                }
            }
            __syncthreads();
        }
    }
    if (tid < Kk) g_sel[b*Kk + tid] = sel2[tid];
}

// ---------------- scores/spans -> out ----------------
__global__ void gather_meta_kernel(const int* __restrict__ spans, float* __restrict__ out) {
    int t = blockIdx.x * 256 + threadIdx.x;
    if (t >= Bz*Kk) return;
    int b = t / Kk;
    int idx = g_sel[t];
    size_t sc_base = (size_t)Bz*Kk*Hh;
    out[sc_base + t] = g_scores[b*Ss + idx];
    size_t sp_base = sc_base + (size_t)Bz*Kk;
    out[sp_base + (size_t)t*2]     = (float)spans[2*idx];
    out[sp_base + (size_t)t*2 + 1] = (float)spans[2*idx + 1];
}

__global__ void fill_tail_kernel(float* out, long long begin, long long end) {
    long long i = begin + blockIdx.x * (long long)blockDim.x + threadIdx.x;
    if (i < end) out[i] = 0.0f;
}

extern "C" void kernel_launch(void* const* d_in, const int* in_sizes, int n_in,
                              void* d_out, int out_size) {
    const float* emb   = (const float*)d_in[0];
    const int*   mask  = (const int*)  d_in[1];
    const int*   spans = (const int*)  d_in[2];
    const float* wemb  = (const float*)d_in[3];
    const float* W1    = (const float*)d_in[4];
    const float* b1    = (const float*)d_in[5];
    const float* w_s   = (const float*)d_in[6];
    const float* b_s   = (const float*)d_in[7];
    float* out = (float*)d_out;
    (void)n_in; (void)in_sizes;

    static int attr_done = 0;
    if (!attr_done) {
        cudaFuncSetAttribute(mma_main, cudaFuncAttributeMaxDynamicSharedMemorySize, MMA_SMEM);
        attr_done = 1;
    }

    long long written = (long long)Bz*Kk*Hh + (long long)Bz*Kk + (long long)Bz*Kk*2;
    if ((long long)out_size > written) {
        long long extra = (long long)out_size - written;
        int blocks = (int)((extra + 255) / 256);
        fill_tail_kernel<<<blocks, 256>>>(out, written, (long long)out_size);
    }

    len_kernel<<<Bz, 256>>>(mask);
    r_kernel<<<MAXW, 256>>>(wemb, W1, b1);
    prep2_kernel<<<768, 256>>>(W1);

    // exact P and Q (scalar fp32)
    sgemm_kernel<0><<<dim3(NBLK, (Bz*Nn)/128, 2), 256>>>(emb, spans, W1, Bz*Nn, nullptr, nullptr);

    // approx main GEMM on tensor cores (HMMA split-2 x 3)
    mma_main<<<dim3(NBLK, MTILES), 256, MMA_SMEM>>>(emb, spans, w_s);

    score_reduce_kernel<<<(Bz*Ss + 255)/256, 256>>>(spans, b_s);
    radix_kernel<<<Bz, 1024>>>(KEXT);
    filter_kernel<<<Bz, 1024>>>();

    // exact rescore of candidates (scalar fp32)
    sgemm_kernel<3><<<dim3(NBLK, (Bz*CAP)/128), 256>>>(emb, spans, W1 + WXY_OFF, Bz*CAP, w_s, nullptr);
    rescore_reduce<<<(Bz*CAP + 255)/256, 256>>>(spans, b_s);

    final_select_kernel<<<Bz, CAP>>>();

    // exact h for selected spans
    sgemm_kernel<2><<<dim3(NBLK, (Bz*Kk + 127)/128), 256>>>(emb, spans, W1 + WXY_OFF, Bz*Kk, nullptr, out);

    gather_meta_kernel<<<(Bz*Kk + 255)/256, 256>>>(spans, out);
}